// round 14
// baseline (speedup 1.0000x reference)
#include <cuda_runtime.h>
#include <cuda_fp16.h>
#include <cstdint>

#define D 512
#define KDIM 512
#define BM 128

static const int MAX_NODES = 50000;
static const int MAX_EDGES = 400000;
static const int MHALF = 25088;              // 196 tiles of 128

__device__ __half g_feath[(size_t)MAX_NODES * D];
__device__ __half g_hh1[(size_t)MAX_NODES * D];
__device__ __half g_hh2[(size_t)MAX_NODES * D];
__device__ __half g_aggh[(size_t)MAX_NODES * D];
__device__ __half g_wth[3 * 512 * 512 + 64 * 512];   // transposed fp16 weights

__device__ int g_deg[MAX_NODES];
__device__ int g_indptr[MAX_NODES + 1];
__device__ int g_cursor[MAX_NODES];
__device__ int g_csr[MAX_EDGES];

// ===========================================================================
// helpers
// ===========================================================================
__device__ __forceinline__ uint32_t smem_to_u32(const void* p) {
    uint32_t a;
    asm("{ .reg .u64 t; cvta.to.shared.u64 t, %1; cvt.u32.u64 %0, t; }"
        : "=r"(a) : "l"(p));
    return a;
}

__device__ __forceinline__ void cp16(uint32_t dst, const void* src, int sz)
{
    asm volatile("cp.async.cg.shared.global [%0], [%1], 16, %2;"
                 :: "r"(dst), "l"(src), "r"(sz) : "memory");
}
#define CP_COMMIT() asm volatile("cp.async.commit_group;" ::: "memory")
#define CP_WAIT0()  asm volatile("cp.async.wait_group 0;" ::: "memory")

__device__ __forceinline__ void mmaH(float* c, const uint32_t* a, uint32_t b0, uint32_t b1)
{
    asm volatile(
        "mma.sync.aligned.m16n8k16.row.col.f32.f16.f16.f32 "
        "{%0,%1,%2,%3}, {%4,%5,%6,%7}, {%8,%9}, {%0,%1,%2,%3};\n"
        : "+f"(c[0]), "+f"(c[1]), "+f"(c[2]), "+f"(c[3])
        : "r"(a[0]), "r"(a[1]), "r"(a[2]), "r"(a[3]), "r"(b0), "r"(b1));
}

__device__ __forceinline__ void ldsm4(uint32_t* r, uint32_t addr)
{
    asm volatile(
        "ldmatrix.sync.aligned.m8n8.x4.shared.b16 {%0,%1,%2,%3}, [%4];"
        : "=r"(r[0]), "=r"(r[1]), "=r"(r[2]), "=r"(r[3]) : "r"(addr));
}

// ===========================================================================
// feat -> fp16
// ===========================================================================
__global__ void feat2half_kernel(const float4* __restrict__ in,
                                 uint4* __restrict__ out, int n8)
{
    int i = blockIdx.x * blockDim.x + threadIdx.x;
    if (i >= n8) return;
    float4 a = __ldg(in + i * 2);
    float4 b = __ldg(in + i * 2 + 1);
    __half2 p0 = __floats2half2_rn(a.x, a.y);
    __half2 p1 = __floats2half2_rn(a.z, a.w);
    __half2 p2 = __floats2half2_rn(b.x, b.y);
    __half2 p3 = __floats2half2_rn(b.z, b.w);
    uint4 o;
    o.x = *reinterpret_cast<uint32_t*>(&p0);
    o.y = *reinterpret_cast<uint32_t*>(&p1);
    o.z = *reinterpret_cast<uint32_t*>(&p2);
    o.w = *reinterpret_cast<uint32_t*>(&p3);
    out[i] = o;
}

// ===========================================================================
// batched weight transpose + fp16 (3 x 512x512)
// ===========================================================================
__global__ void transpose3_half_kernel(const float* __restrict__ in0,
                                       const float* __restrict__ in1,
                                       const float* __restrict__ in2,
                                       __half* __restrict__ out0,
                                       __half* __restrict__ out1,
                                       __half* __restrict__ out2)
{
    __shared__ float tile[32][33];
    const float* in  = (blockIdx.z == 0) ? in0 : (blockIdx.z == 1) ? in1 : in2;
    __half*     out  = (blockIdx.z == 0) ? out0 : (blockIdx.z == 1) ? out1 : out2;
    const int k0 = blockIdx.x * 32;
    const int n0 = blockIdx.y * 32;
    const int tx = threadIdx.x;
    const int ty = threadIdx.y;
#pragma unroll
    for (int i = 0; i < 32; i += 8)
        tile[ty + i][tx] = __ldg(in + (size_t)(k0 + ty + i) * 512 + n0 + tx);
    __syncthreads();
#pragma unroll
    for (int i = 0; i < 32; i += 8)
        out[(size_t)(n0 + ty + i) * 512 + k0 + tx] = __float2half_rn(tile[tx][ty + i]);
}

__global__ void transpose_half_kernel(const float* __restrict__ in,
                                      __half* __restrict__ out,
                                      int K, int Ncols)
{
    __shared__ float tile[32][33];
    const int k0 = blockIdx.x * 32;
    const int n0 = blockIdx.y * 32;
    const int tx = threadIdx.x;
    const int ty = threadIdx.y;
#pragma unroll
    for (int i = 0; i < 32; i += 8) {
        int k = k0 + ty + i, n = n0 + tx;
        tile[ty + i][tx] = (k < K && n < Ncols) ? __ldg(in + (size_t)k * Ncols + n) : 0.f;
    }
    __syncthreads();
#pragma unroll
    for (int i = 0; i < 32; i += 8) {
        int n = n0 + ty + i, k = k0 + tx;
        if (n < Ncols && k < K)
            out[(size_t)n * K + k] = __float2half_rn(tile[tx][ty + i]);
    }
}

// ===========================================================================
// CSR build
// ===========================================================================
__global__ void hist_kernel(const int* __restrict__ dst, int* __restrict__ deg,
                            int n_edges)
{
    int e = blockIdx.x * blockDim.x + threadIdx.x;
    if (e < n_edges) atomicAdd(&deg[__ldg(dst + e)], 1);
}

__global__ void scan_kernel(const int* __restrict__ deg, int* __restrict__ indptr,
                            int n)
{
    const int T = 1024;
    __shared__ int sh[T];
    int t = threadIdx.x;
    int chunk = (n + T - 1) / T;
    int beg = t * chunk;
    int end = min(beg + chunk, n);
    int s = 0;
    for (int i = beg; i < end; i++) s += deg[i];
    sh[t] = s;
    __syncthreads();
    for (int off = 1; off < T; off <<= 1) {
        int v = sh[t];
        int u = (t >= off) ? sh[t - off] : 0;
        __syncthreads();
        sh[t] = v + u;
        __syncthreads();
    }
    int run = (t == 0) ? 0 : sh[t - 1];
    for (int i = beg; i < end; i++) { indptr[i] = run; run += deg[i]; }
    if (t == T - 1) indptr[n] = sh[T - 1];
}

__global__ void fill_kernel(const int* __restrict__ src, const int* __restrict__ dst,
                            const int* __restrict__ indptr, int* __restrict__ cursor,
                            int* __restrict__ csr, int n_edges)
{
    int e = blockIdx.x * blockDim.x + threadIdx.x;
    if (e >= n_edges) return;
    int d = __ldg(dst + e);
    int pos = __ldg(indptr + d) + atomicAdd(&cursor[d], 1);
    csr[pos] = __ldg(src + e);
}

// ===========================================================================
// Gather aggregation: 64 threads/node, LDG.128, 4-deep MLP unroll.
// node range [nodeStart, nodeStart + gridDim.x)
// ===========================================================================
__device__ __forceinline__ void add8(float* a, uint4 v)
{
    float2 g0 = __half22float2(*reinterpret_cast<__half2*>(&v.x));
    float2 g1 = __half22float2(*reinterpret_cast<__half2*>(&v.y));
    float2 g2 = __half22float2(*reinterpret_cast<__half2*>(&v.z));
    float2 g3 = __half22float2(*reinterpret_cast<__half2*>(&v.w));
    a[0] += g0.x; a[1] += g0.y; a[2] += g1.x; a[3] += g1.y;
    a[4] += g2.x; a[5] += g2.y; a[6] += g3.x; a[7] += g3.y;
}

__global__ __launch_bounds__(64)
void gather_agg_h(const uint4* __restrict__ h, const int* __restrict__ indptr,
                  const int* __restrict__ csr, uint4* __restrict__ out,
                  int nodeStart)
{
    __shared__ int nb[64];
    const int node = nodeStart + blockIdx.x;
    const int t = threadIdx.x;

    float a[8];
#pragma unroll
    for (int j = 0; j < 8; j++) a[j] = 0.f;
    add8(a, __ldg(h + (size_t)node * 64 + t));

    const int beg = __ldg(indptr + node);
    const int end = __ldg(indptr + node + 1);
    for (int base = beg; base < end; base += 64) {
        int cnt = min(64, end - base);
        if (t < cnt) nb[t] = __ldg(csr + base + t);
        __syncthreads();
        int i = 0;
        for (; i + 4 <= cnt; i += 4) {
            uint4 v0 = __ldg(h + (size_t)nb[i + 0] * 64 + t);
            uint4 v1 = __ldg(h + (size_t)nb[i + 1] * 64 + t);
            uint4 v2 = __ldg(h + (size_t)nb[i + 2] * 64 + t);
            uint4 v3 = __ldg(h + (size_t)nb[i + 3] * 64 + t);
            add8(a, v0); add8(a, v1); add8(a, v2); add8(a, v3);
        }
        for (; i < cnt; i++)
            add8(a, __ldg(h + (size_t)nb[i] * 64 + t));
        __syncthreads();
    }
    __half2 p0 = __floats2half2_rn(a[0], a[1]);
    __half2 p1 = __floats2half2_rn(a[2], a[3]);
    __half2 p2 = __floats2half2_rn(a[4], a[5]);
    __half2 p3 = __floats2half2_rn(a[6], a[7]);
    uint4 o;
    o.x = *reinterpret_cast<uint32_t*>(&p0);
    o.y = *reinterpret_cast<uint32_t*>(&p1);
    o.z = *reinterpret_cast<uint32_t*>(&p2);
    o.w = *reinterpret_cast<uint32_t*>(&p3);
    __stcs(out + (size_t)node * 64 + t, o);
}

// ===========================================================================
// fp16 mma.sync GEMM, 2-stage double buffer, 3 CTAs/SM.
// Warp grid 2 x WN (64x64 warp tiles).  WN=2: BN=128.  WN=1: BN=64.
// M rows offset by mBase (for half-pipelining).
// ===========================================================================
#define HBK 64
#define HKT (KDIM / HBK)          // 8
#define HPITCH 72                 // halves per row (144B = 9 x 16B units)
#define HPB (HPITCH * 2)
#define HAS_B (128 * HPB)         // A stage: 18432 B

template<int WN, bool RELU, bool OUTH>
__global__ __launch_bounds__(64 * WN, 3)
void gin_hgemm(const __half* __restrict__ A, const __half* __restrict__ Bt,
               const float* __restrict__ bias, void* __restrict__ CoutV,
               int M, int N, int mBase)
{
    constexpr int THREADS = 64 * WN;
    constexpr int BN      = 64 * WN;
    constexpr int BS_B    = BN * HPB;
    constexpr int STG     = HAS_B + BS_B;

    extern __shared__ char smem[];
    const uint32_t sb = smem_to_u32(smem);

    const int tid  = threadIdx.x;
    const int wid  = tid >> 5;
    const int lane = tid & 31;
    const int wm   = wid & 1;
    const int wn   = wid >> 1;
    const int grp  = lane >> 2;
    const int tig  = lane & 3;

    const int m0 = mBase + blockIdx.x * BM;
    const int n0 = blockIdx.y * BN;

    float acc[4][8][4];
#pragma unroll
    for (int mi = 0; mi < 4; mi++)
#pragma unroll
        for (int ni = 0; ni < 8; ni++)
#pragma unroll
            for (int j = 0; j < 4; j++) acc[mi][ni][j] = 0.f;

    const uint32_t aOff = (uint32_t)((wm * 64 + (lane & 15)) * HPB + (lane >> 4) * 16);
    const uint32_t bOff = (uint32_t)((wn * 64 + (lane & 7) + ((lane >> 4) & 1) * 8) * HPB
                                     + ((lane >> 3) & 1) * 16);

    auto issue = [&](int kt, int st) {
        const int kbase = kt * HBK;
        const uint32_t sA = sb + st * STG;
        const uint32_t sB = sA + HAS_B;
#pragma unroll
        for (int i = 0; i < 1024 / THREADS; i++) {
            int idx = tid + i * THREADS;
            int row = idx >> 3;
            int u   = idx & 7;
            int gr  = m0 + row;
            bool ok = (gr < M);
            const __half* src = ok ? (A + (size_t)gr * KDIM + kbase + u * 8) : A;
            cp16(sA + row * HPB + u * 16, src, ok ? 16 : 0);
        }
#pragma unroll
        for (int i = 0; i < (BN * 8) / THREADS; i++) {
            int idx = tid + i * THREADS;
            int row = idx >> 3;
            int u   = idx & 7;
            int gn  = n0 + row;
            bool ok = (gn < N);
            const __half* src = ok ? (Bt + (size_t)gn * KDIM + kbase + u * 8) : Bt;
            cp16(sB + row * HPB + u * 16, src, ok ? 16 : 0);
        }
    };

    auto compute = [&](int st) {
        const uint32_t aBase = sb + st * STG + aOff;
        const uint32_t bBase = sb + st * STG + HAS_B + bOff;
#pragma unroll
        for (int s = 0; s < 4; s++) {
            const uint32_t ks = s * 32;
            uint32_t af[4][4];
#pragma unroll
            for (int mi = 0; mi < 4; mi++)
                ldsm4(af[mi], aBase + mi * 16 * HPB + ks);
#pragma unroll
            for (int p = 0; p < 4; p++) {
                uint32_t bf[4];
                ldsm4(bf, bBase + p * 16 * HPB + ks);
#pragma unroll
                for (int mi = 0; mi < 4; mi++) {
                    mmaH(acc[mi][2 * p],     af[mi], bf[0], bf[1]);
                    mmaH(acc[mi][2 * p + 1], af[mi], bf[2], bf[3]);
                }
            }
        }
    };

    issue(0, 0); CP_COMMIT();
    for (int kt = 0; kt < HKT; kt++) {
        CP_WAIT0();
        __syncthreads();
        const int nx = kt + 1;
        if (nx < HKT) { issue(nx, nx & 1); CP_COMMIT(); }
        compute(kt & 1);
    }

    // ---- epilogue ----
#pragma unroll
    for (int nt = 0; nt < 8; nt++) {
        int col = n0 + wn * 64 + nt * 8 + tig * 2;
        if (col >= N) continue;
        float bv0 = __ldg(bias + col);
        float bv1 = __ldg(bias + col + 1);
#pragma unroll
        for (int mi = 0; mi < 4; mi++) {
            int rbase = m0 + wm * 64 + mi * 16 + grp;
#pragma unroll
            for (int h = 0; h < 2; h++) {
                int r = rbase + h * 8;
                if (r >= M) continue;
                float x0 = acc[mi][nt][h * 2 + 0] + bv0;
                float x1 = acc[mi][nt][h * 2 + 1] + bv1;
                if (RELU) { x0 = fmaxf(x0, 0.f); x1 = fmaxf(x1, 0.f); }
                if (OUTH) {
                    __half2 p = __floats2half2_rn(x0, x1);
                    *reinterpret_cast<__half2*>((__half*)CoutV + (size_t)r * N + col) = p;
                } else {
                    float2 o; o.x = x0; o.y = x1;
                    *reinterpret_cast<float2*>((float*)CoutV + (size_t)r * N + col) = o;
                }
            }
        }
    }
}

#define HSMEM_L (2 * (HAS_B + 128 * HPB))      // 73728
#define HSMEM_C (2 * (HAS_B + 64 * HPB))       // 55296

// ===========================================================================
// Launch: two-stream software pipeline (gather ∥ GEMM within each layer)
// ===========================================================================
extern "C" void kernel_launch(void* const* d_in, const int* in_sizes, int n_in,
                              void* d_out, int out_size)
{
    const float* feat = (const float*)d_in[0];
    const int*   src  = (const int*)d_in[1];
    const int*   dst  = (const int*)d_in[2];
    const float* W0   = (const float*)d_in[3];
    const float* b0   = (const float*)d_in[4];
    const float* W1   = (const float*)d_in[5];
    const float* b1   = (const float*)d_in[6];
    const float* W2   = (const float*)d_in[7];
    const float* b2   = (const float*)d_in[8];
    const float* Wc   = (const float*)d_in[9];
    const float* bc   = (const float*)d_in[10];

    const int n_nodes = in_sizes[0] / D;
    const int n_edges = in_sizes[1];
    const int n_cls   = in_sizes[10];

    __half *feath, *hh1, *hh2, *aggh, *wth;
    int *deg, *indptr, *cursor, *csr;
    cudaGetSymbolAddress((void**)&feath, g_feath);
    cudaGetSymbolAddress((void**)&hh1, g_hh1);
    cudaGetSymbolAddress((void**)&hh2, g_hh2);
    cudaGetSymbolAddress((void**)&aggh, g_aggh);
    cudaGetSymbolAddress((void**)&wth, g_wth);
    cudaGetSymbolAddress((void**)&deg, g_deg);
    cudaGetSymbolAddress((void**)&indptr, g_indptr);
    cudaGetSymbolAddress((void**)&cursor, g_cursor);
    cudaGetSymbolAddress((void**)&csr, g_csr);

    __half* W0t = wth;
    __half* W1t = wth + 262144;
    __half* W2t = wth + 524288;
    __half* Wct = wth + 786432;

    cudaFuncSetAttribute(gin_hgemm<2, true, true>,
                         cudaFuncAttributeMaxDynamicSharedMemorySize, HSMEM_L);
    cudaFuncSetAttribute(gin_hgemm<1, false, false>,
                         cudaFuncAttributeMaxDynamicSharedMemorySize, HSMEM_C);

    // ---- lazy one-time host resources (no device memory involved) ----
    static cudaStream_t s1 = nullptr;
    static cudaEvent_t evF = nullptr, evW = nullptr;
    static cudaEvent_t evA[3] = {nullptr, nullptr, nullptr};
    static cudaEvent_t evB[3] = {nullptr, nullptr, nullptr};
    if (!s1) {
        cudaStreamCreateWithFlags(&s1, cudaStreamNonBlocking);
        cudaEventCreateWithFlags(&evF, cudaEventDisableTiming);
        cudaEventCreateWithFlags(&evW, cudaEventDisableTiming);
        for (int i = 0; i < 3; i++) {
            cudaEventCreateWithFlags(&evA[i], cudaEventDisableTiming);
            cudaEventCreateWithFlags(&evB[i], cudaEventDisableTiming);
        }
    }

    const int eBlocks = (n_edges + 255) / 256;

    const int nA = MHALF;                         // 25088 nodes, 196 tiles
    const int nB = n_nodes - MHALF;               // remainder
    const int tA = nA / BM;                       // 196
    const int tB = (nB + BM - 1) / BM;            // 195

    // ---- fork: weight transposes on s1 ----
    cudaEventRecord(evF, 0);
    cudaStreamWaitEvent(s1, evF, 0);
    {
        dim3 tb(32, 8);
        dim3 tg3(16, 16, 3);
        transpose3_half_kernel<<<tg3, tb, 0, s1>>>(W0, W1, W2, W0t, W1t, W2t);
        dim3 tgc(16, (n_cls + 31) / 32);
        transpose_half_kernel<<<tgc, tb, 0, s1>>>(Wc, Wct, KDIM, n_cls);
    }
    cudaEventRecord(evW, s1);

    // ---- s0: feat->fp16 + CSR build ----
    const int n8 = (n_nodes * D) / 8;
    feat2half_kernel<<<(n8 + 255) / 256, 256>>>((const float4*)feat,
                                                (uint4*)feath, n8);
    cudaMemsetAsync(deg, 0, (size_t)n_nodes * sizeof(int));
    cudaMemsetAsync(cursor, 0, (size_t)n_nodes * sizeof(int));
    hist_kernel<<<eBlocks, 256>>>(dst, deg, n_edges);
    scan_kernel<<<1, 1024>>>(deg, indptr, n_nodes);
    fill_kernel<<<eBlocks, 256>>>(src, dst, indptr, cursor, csr, n_edges);
    cudaStreamWaitEvent(0, evW, 0);      // weights ready before any GEMM

    const __half* Xs[3] = { feath, hh1, hh2 };
    __half*       Ys[3] = { hh1, hh2, hh1 };
    const __half* Wt[3] = { W0t, W1t, W2t };
    const float*  Bs[3] = { b0, b1, b2 };

    dim3 gA(tA, 4), gB(tB, 4);

    for (int L = 0; L < 3; L++) {
        // gather half A on s0
        gather_agg_h<<<nA, 64>>>((const uint4*)Xs[L], indptr, csr,
                                 (uint4*)aggh, 0);
        cudaEventRecord(evA[L], 0);
        // gather half B on s1 (after gA; overlaps GEMM A)
        cudaStreamWaitEvent(s1, evA[L], 0);
        gather_agg_h<<<nB, 64, 0, s1>>>((const uint4*)Xs[L], indptr, csr,
                                        (uint4*)aggh, nA);
        // GEMM half A on s0
        gin_hgemm<2, true, true><<<gA, 128, HSMEM_L>>>(
            aggh, Wt[L], Bs[L], Ys[L], n_nodes, D, 0);
        // GEMM half B on s1
        gin_hgemm<2, true, true><<<gB, 128, HSMEM_L, s1>>>(
            aggh, Wt[L], Bs[L], Ys[L], n_nodes, D, nA);
        cudaEventRecord(evB[L], s1);
        cudaStreamWaitEvent(0, evB[L], 0);   // join before next layer
    }

    // classifier on s0 (full M)
    dim3 cGrid((n_nodes + BM - 1) / BM, 1);
    gin_hgemm<1, false, false><<<cGrid, 64, HSMEM_C>>>(
        hh1, Wct, bc, (float*)d_out, n_nodes, n_cls, 0);
}

// round 15
// speedup vs baseline: 1.0386x; 1.0386x over previous
#include <cuda_runtime.h>
#include <cuda_fp16.h>
#include <cstdint>

#define D 512
#define KDIM 512
#define BM 128

static const int MAX_NODES = 50000;
static const int MAX_EDGES = 400000;

__device__ __half g_feath[(size_t)MAX_NODES * D];
__device__ __half g_hh1[(size_t)MAX_NODES * D];
__device__ __half g_hh2[(size_t)MAX_NODES * D];
__device__ __half g_aggh[(size_t)MAX_NODES * D];
__device__ __half g_wth[3 * 512 * 512 + 64 * 512];   // transposed fp16 weights

__device__ int g_degcur[2 * MAX_NODES];              // [deg | cursor] one memset
__device__ int g_indptr[MAX_NODES + 1];
__device__ int g_csr[MAX_EDGES];

// ===========================================================================
// helpers
// ===========================================================================
__device__ __forceinline__ uint32_t smem_to_u32(const void* p) {
    uint32_t a;
    asm("{ .reg .u64 t; cvta.to.shared.u64 t, %1; cvt.u32.u64 %0, t; }"
        : "=r"(a) : "l"(p));
    return a;
}

__device__ __forceinline__ void cp16(uint32_t dst, const void* src, int sz)
{
    asm volatile("cp.async.cg.shared.global [%0], [%1], 16, %2;"
                 :: "r"(dst), "l"(src), "r"(sz) : "memory");
}
#define CP_COMMIT() asm volatile("cp.async.commit_group;" ::: "memory")
#define CP_WAIT0()  asm volatile("cp.async.wait_group 0;" ::: "memory")

__device__ __forceinline__ void mmaH(float* c, const uint32_t* a, uint32_t b0, uint32_t b1)
{
    asm volatile(
        "mma.sync.aligned.m16n8k16.row.col.f32.f16.f16.f32 "
        "{%0,%1,%2,%3}, {%4,%5,%6,%7}, {%8,%9}, {%0,%1,%2,%3};\n"
        : "+f"(c[0]), "+f"(c[1]), "+f"(c[2]), "+f"(c[3])
        : "r"(a[0]), "r"(a[1]), "r"(a[2]), "r"(a[3]), "r"(b0), "r"(b1));
}

__device__ __forceinline__ void ldsm4(uint32_t* r, uint32_t addr)
{
    asm volatile(
        "ldmatrix.sync.aligned.m8n8.x4.shared.b16 {%0,%1,%2,%3}, [%4];"
        : "=r"(r[0]), "=r"(r[1]), "=r"(r[2]), "=r"(r[3]) : "r"(addr));
}

// ===========================================================================
// feat -> fp16
// ===========================================================================
__global__ void feat2half_kernel(const float4* __restrict__ in,
                                 uint4* __restrict__ out, int n8)
{
    int i = blockIdx.x * blockDim.x + threadIdx.x;
    if (i >= n8) return;
    float4 a = __ldg(in + i * 2);
    float4 b = __ldg(in + i * 2 + 1);
    __half2 p0 = __floats2half2_rn(a.x, a.y);
    __half2 p1 = __floats2half2_rn(a.z, a.w);
    __half2 p2 = __floats2half2_rn(b.x, b.y);
    __half2 p3 = __floats2half2_rn(b.z, b.w);
    uint4 o;
    o.x = *reinterpret_cast<uint32_t*>(&p0);
    o.y = *reinterpret_cast<uint32_t*>(&p1);
    o.z = *reinterpret_cast<uint32_t*>(&p2);
    o.w = *reinterpret_cast<uint32_t*>(&p3);
    out[i] = o;
}

// ===========================================================================
// batched weight transpose + fp16 (3 x 512x512)
// ===========================================================================
__global__ void transpose3_half_kernel(const float* __restrict__ in0,
                                       const float* __restrict__ in1,
                                       const float* __restrict__ in2,
                                       __half* __restrict__ out0,
                                       __half* __restrict__ out1,
                                       __half* __restrict__ out2)
{
    __shared__ float tile[32][33];
    const float* in  = (blockIdx.z == 0) ? in0 : (blockIdx.z == 1) ? in1 : in2;
    __half*     out  = (blockIdx.z == 0) ? out0 : (blockIdx.z == 1) ? out1 : out2;
    const int k0 = blockIdx.x * 32;
    const int n0 = blockIdx.y * 32;
    const int tx = threadIdx.x;
    const int ty = threadIdx.y;
#pragma unroll
    for (int i = 0; i < 32; i += 8)
        tile[ty + i][tx] = __ldg(in + (size_t)(k0 + ty + i) * 512 + n0 + tx);
    __syncthreads();
#pragma unroll
    for (int i = 0; i < 32; i += 8)
        out[(size_t)(n0 + ty + i) * 512 + k0 + tx] = __float2half_rn(tile[tx][ty + i]);
}

__global__ void transpose_half_kernel(const float* __restrict__ in,
                                      __half* __restrict__ out,
                                      int K, int Ncols)
{
    __shared__ float tile[32][33];
    const int k0 = blockIdx.x * 32;
    const int n0 = blockIdx.y * 32;
    const int tx = threadIdx.x;
    const int ty = threadIdx.y;
#pragma unroll
    for (int i = 0; i < 32; i += 8) {
        int k = k0 + ty + i, n = n0 + tx;
        tile[ty + i][tx] = (k < K && n < Ncols) ? __ldg(in + (size_t)k * Ncols + n) : 0.f;
    }
    __syncthreads();
#pragma unroll
    for (int i = 0; i < 32; i += 8) {
        int n = n0 + ty + i, k = k0 + tx;
        if (n < Ncols && k < K)
            out[(size_t)n * K + k] = __float2half_rn(tile[tx][ty + i]);
    }
}

// ===========================================================================
// CSR build
// ===========================================================================
__global__ void hist_kernel(const int* __restrict__ dst, int* __restrict__ deg,
                            int n_edges)
{
    int e = blockIdx.x * blockDim.x + threadIdx.x;
    if (e < n_edges) atomicAdd(&deg[__ldg(dst + e)], 1);
}

__global__ void scan_kernel(const int* __restrict__ deg, int* __restrict__ indptr,
                            int n)
{
    const int T = 1024;
    __shared__ int sh[T];
    int t = threadIdx.x;
    int chunk = (n + T - 1) / T;
    int beg = t * chunk;
    int end = min(beg + chunk, n);
    int s = 0;
    for (int i = beg; i < end; i++) s += deg[i];
    sh[t] = s;
    __syncthreads();
    for (int off = 1; off < T; off <<= 1) {
        int v = sh[t];
        int u = (t >= off) ? sh[t - off] : 0;
        __syncthreads();
        sh[t] = v + u;
        __syncthreads();
    }
    int run = (t == 0) ? 0 : sh[t - 1];
    for (int i = beg; i < end; i++) { indptr[i] = run; run += deg[i]; }
    if (t == T - 1) indptr[n] = sh[T - 1];
}

__global__ void fill_kernel(const int* __restrict__ src, const int* __restrict__ dst,
                            const int* __restrict__ indptr, int* __restrict__ cursor,
                            int* __restrict__ csr, int n_edges)
{
    int e = blockIdx.x * blockDim.x + threadIdx.x;
    if (e >= n_edges) return;
    int d = __ldg(dst + e);
    int pos = __ldg(indptr + d) + atomicAdd(&cursor[d], 1);
    csr[pos] = __ldg(src + e);
}

// ===========================================================================
// Gather aggregation: 64 threads/node, LDG.128, 4-deep MLP unroll.
// ===========================================================================
__device__ __forceinline__ void add8(float* a, uint4 v)
{
    float2 g0 = __half22float2(*reinterpret_cast<__half2*>(&v.x));
    float2 g1 = __half22float2(*reinterpret_cast<__half2*>(&v.y));
    float2 g2 = __half22float2(*reinterpret_cast<__half2*>(&v.z));
    float2 g3 = __half22float2(*reinterpret_cast<__half2*>(&v.w));
    a[0] += g0.x; a[1] += g0.y; a[2] += g1.x; a[3] += g1.y;
    a[4] += g2.x; a[5] += g2.y; a[6] += g3.x; a[7] += g3.y;
}

__global__ __launch_bounds__(64)
void gather_agg_h(const uint4* __restrict__ h, const int* __restrict__ indptr,
                  const int* __restrict__ csr, uint4* __restrict__ out)
{
    __shared__ int nb[64];
    const int node = blockIdx.x;
    const int t = threadIdx.x;

    float a[8];
#pragma unroll
    for (int j = 0; j < 8; j++) a[j] = 0.f;
    add8(a, __ldg(h + (size_t)node * 64 + t));

    const int beg = __ldg(indptr + node);
    const int end = __ldg(indptr + node + 1);
    for (int base = beg; base < end; base += 64) {
        int cnt = min(64, end - base);
        if (t < cnt) nb[t] = __ldg(csr + base + t);
        __syncthreads();
        int i = 0;
        for (; i + 4 <= cnt; i += 4) {
            uint4 v0 = __ldg(h + (size_t)nb[i + 0] * 64 + t);
            uint4 v1 = __ldg(h + (size_t)nb[i + 1] * 64 + t);
            uint4 v2 = __ldg(h + (size_t)nb[i + 2] * 64 + t);
            uint4 v3 = __ldg(h + (size_t)nb[i + 3] * 64 + t);
            add8(a, v0); add8(a, v1); add8(a, v2); add8(a, v3);
        }
        for (; i < cnt; i++)
            add8(a, __ldg(h + (size_t)nb[i] * 64 + t));
        __syncthreads();
    }
    __half2 p0 = __floats2half2_rn(a[0], a[1]);
    __half2 p1 = __floats2half2_rn(a[2], a[3]);
    __half2 p2 = __floats2half2_rn(a[4], a[5]);
    __half2 p3 = __floats2half2_rn(a[6], a[7]);
    uint4 o;
    o.x = *reinterpret_cast<uint32_t*>(&p0);
    o.y = *reinterpret_cast<uint32_t*>(&p1);
    o.z = *reinterpret_cast<uint32_t*>(&p2);
    o.w = *reinterpret_cast<uint32_t*>(&p3);
    __stcs(out + (size_t)node * 64 + t, o);
}

// ===========================================================================
// fp16 mma.sync GEMM, 2-stage double buffer, 3 CTAs/SM.
// Warp grid 2 x WN (64x64 warp tiles).  WN=2: BN=128.  WN=1: BN=64.
// ===========================================================================
#define HBK 64
#define HKT (KDIM / HBK)          // 8
#define HPITCH 72                 // halves per row (144B = 9 x 16B units)
#define HPB (HPITCH * 2)
#define HAS_B (128 * HPB)         // A stage: 18432 B

template<int WN, bool RELU, bool OUTH>
__global__ __launch_bounds__(64 * WN, 3)
void gin_hgemm(const __half* __restrict__ A, const __half* __restrict__ Bt,
               const float* __restrict__ bias, void* __restrict__ CoutV,
               int M, int N)
{
    constexpr int THREADS = 64 * WN;
    constexpr int BN      = 64 * WN;
    constexpr int BS_B    = BN * HPB;
    constexpr int STG     = HAS_B + BS_B;

    extern __shared__ char smem[];
    const uint32_t sb = smem_to_u32(smem);

    const int tid  = threadIdx.x;
    const int wid  = tid >> 5;
    const int lane = tid & 31;
    const int wm   = wid & 1;
    const int wn   = wid >> 1;
    const int grp  = lane >> 2;
    const int tig  = lane & 3;

    const int m0 = blockIdx.x * BM;
    const int n0 = blockIdx.y * BN;

    float acc[4][8][4];
#pragma unroll
    for (int mi = 0; mi < 4; mi++)
#pragma unroll
        for (int ni = 0; ni < 8; ni++)
#pragma unroll
            for (int j = 0; j < 4; j++) acc[mi][ni][j] = 0.f;

    const uint32_t aOff = (uint32_t)((wm * 64 + (lane & 15)) * HPB + (lane >> 4) * 16);
    const uint32_t bOff = (uint32_t)((wn * 64 + (lane & 7) + ((lane >> 4) & 1) * 8) * HPB
                                     + ((lane >> 3) & 1) * 16);

    auto issue = [&](int kt, int st) {
        const int kbase = kt * HBK;
        const uint32_t sA = sb + st * STG;
        const uint32_t sB = sA + HAS_B;
#pragma unroll
        for (int i = 0; i < 1024 / THREADS; i++) {
            int idx = tid + i * THREADS;
            int row = idx >> 3;
            int u   = idx & 7;
            int gr  = m0 + row;
            bool ok = (gr < M);
            const __half* src = ok ? (A + (size_t)gr * KDIM + kbase + u * 8) : A;
            cp16(sA + row * HPB + u * 16, src, ok ? 16 : 0);
        }
#pragma unroll
        for (int i = 0; i < (BN * 8) / THREADS; i++) {
            int idx = tid + i * THREADS;
            int row = idx >> 3;
            int u   = idx & 7;
            int gn  = n0 + row;
            bool ok = (gn < N);
            const __half* src = ok ? (Bt + (size_t)gn * KDIM + kbase + u * 8) : Bt;
            cp16(sB + row * HPB + u * 16, src, ok ? 16 : 0);
        }
    };

    auto compute = [&](int st) {
        const uint32_t aBase = sb + st * STG + aOff;
        const uint32_t bBase = sb + st * STG + HAS_B + bOff;
#pragma unroll
        for (int s = 0; s < 4; s++) {
            const uint32_t ks = s * 32;
            uint32_t af[4][4];
#pragma unroll
            for (int mi = 0; mi < 4; mi++)
                ldsm4(af[mi], aBase + mi * 16 * HPB + ks);
#pragma unroll
            for (int p = 0; p < 4; p++) {
                uint32_t bf[4];
                ldsm4(bf, bBase + p * 16 * HPB + ks);
#pragma unroll
                for (int mi = 0; mi < 4; mi++) {
                    mmaH(acc[mi][2 * p],     af[mi], bf[0], bf[1]);
                    mmaH(acc[mi][2 * p + 1], af[mi], bf[2], bf[3]);
                }
            }
        }
    };

    issue(0, 0); CP_COMMIT();
    for (int kt = 0; kt < HKT; kt++) {
        CP_WAIT0();
        __syncthreads();
        const int nx = kt + 1;
        if (nx < HKT) { issue(nx, nx & 1); CP_COMMIT(); }
        compute(kt & 1);
    }

    // ---- epilogue ----
#pragma unroll
    for (int nt = 0; nt < 8; nt++) {
        int col = n0 + wn * 64 + nt * 8 + tig * 2;
        if (col >= N) continue;
        float bv0 = __ldg(bias + col);
        float bv1 = __ldg(bias + col + 1);
#pragma unroll
        for (int mi = 0; mi < 4; mi++) {
            int rbase = m0 + wm * 64 + mi * 16 + grp;
#pragma unroll
            for (int h = 0; h < 2; h++) {
                int r = rbase + h * 8;
                if (r >= M) continue;
                float x0 = acc[mi][nt][h * 2 + 0] + bv0;
                float x1 = acc[mi][nt][h * 2 + 1] + bv1;
                if (RELU) { x0 = fmaxf(x0, 0.f); x1 = fmaxf(x1, 0.f); }
                if (OUTH) {
                    __half2 p = __floats2half2_rn(x0, x1);
                    *reinterpret_cast<__half2*>((__half*)CoutV + (size_t)r * N + col) = p;
                } else {
                    float2 o; o.x = x0; o.y = x1;
                    *reinterpret_cast<float2*>((float*)CoutV + (size_t)r * N + col) = o;
                }
            }
        }
    }
}

#define HSMEM_L (2 * (HAS_B + 128 * HPB))      // 73728
#define HSMEM_C (2 * (HAS_B + 64 * HPB))       // 55296

// ===========================================================================
// Launch: serial main chain; setup phase forked across two streams
// ===========================================================================
extern "C" void kernel_launch(void* const* d_in, const int* in_sizes, int n_in,
                              void* d_out, int out_size)
{
    const float* feat = (const float*)d_in[0];
    const int*   src  = (const int*)d_in[1];
    const int*   dst  = (const int*)d_in[2];
    const float* W0   = (const float*)d_in[3];
    const float* b0   = (const float*)d_in[4];
    const float* W1   = (const float*)d_in[5];
    const float* b1   = (const float*)d_in[6];
    const float* W2   = (const float*)d_in[7];
    const float* b2   = (const float*)d_in[8];
    const float* Wc   = (const float*)d_in[9];
    const float* bc   = (const float*)d_in[10];

    const int n_nodes = in_sizes[0] / D;
    const int n_edges = in_sizes[1];
    const int n_cls   = in_sizes[10];

    __half *feath, *hh1, *hh2, *aggh, *wth;
    int *degcur, *indptr, *csr;
    cudaGetSymbolAddress((void**)&feath, g_feath);
    cudaGetSymbolAddress((void**)&hh1, g_hh1);
    cudaGetSymbolAddress((void**)&hh2, g_hh2);
    cudaGetSymbolAddress((void**)&aggh, g_aggh);
    cudaGetSymbolAddress((void**)&wth, g_wth);
    cudaGetSymbolAddress((void**)&degcur, g_degcur);
    cudaGetSymbolAddress((void**)&indptr, g_indptr);
    cudaGetSymbolAddress((void**)&csr, g_csr);

    int* deg    = degcur;
    int* cursor = degcur + MAX_NODES;

    __half* W0t = wth;
    __half* W1t = wth + 262144;
    __half* W2t = wth + 524288;
    __half* Wct = wth + 786432;

    cudaFuncSetAttribute(gin_hgemm<2, true, true>,
                         cudaFuncAttributeMaxDynamicSharedMemorySize, HSMEM_L);
    cudaFuncSetAttribute(gin_hgemm<1, false, false>,
                         cudaFuncAttributeMaxDynamicSharedMemorySize, HSMEM_C);

    // ---- lazy one-time host resources (no device memory) ----
    static cudaStream_t s1 = nullptr;
    static cudaEvent_t evF = nullptr, evS = nullptr;
    if (!s1) {
        cudaStreamCreateWithFlags(&s1, cudaStreamNonBlocking);
        cudaEventCreateWithFlags(&evF, cudaEventDisableTiming);
        cudaEventCreateWithFlags(&evS, cudaEventDisableTiming);
    }

    const int eBlocks = (n_edges + 255) / 256;

    // ---- fork: feat->fp16 + weight transposes on s1;  CSR build on s0 ----
    cudaEventRecord(evF, 0);
    cudaStreamWaitEvent(s1, evF, 0);
    {
        const int n8 = (n_nodes * D) / 8;
        feat2half_kernel<<<(n8 + 255) / 256, 256, 0, s1>>>(
            (const float4*)feat, (uint4*)feath, n8);
        dim3 tb(32, 8);
        dim3 tg3(16, 16, 3);
        transpose3_half_kernel<<<tg3, tb, 0, s1>>>(W0, W1, W2, W0t, W1t, W2t);
        dim3 tgc(16, (n_cls + 31) / 32);
        transpose_half_kernel<<<tgc, tb, 0, s1>>>(Wc, Wct, KDIM, n_cls);
    }
    cudaEventRecord(evS, s1);

    cudaMemsetAsync(degcur, 0, (size_t)2 * MAX_NODES * sizeof(int));
    hist_kernel<<<eBlocks, 256>>>(dst, deg, n_edges);
    scan_kernel<<<1, 1024>>>(deg, indptr, n_nodes);
    fill_kernel<<<eBlocks, 256>>>(src, dst, indptr, cursor, csr, n_edges);
    cudaStreamWaitEvent(0, evS, 0);      // join: feath + weights ready

    dim3 gGrid((n_nodes + BM - 1) / BM, 4);
    dim3 cGrid((n_nodes + BM - 1) / BM, 1);

    // Layer 0
    gather_agg_h<<<n_nodes, 64>>>((const uint4*)feath, indptr, csr, (uint4*)aggh);
    gin_hgemm<2, true, true><<<gGrid, 128, HSMEM_L>>>(aggh, W0t, b0, hh1, n_nodes, D);

    // Layer 1
    gather_agg_h<<<n_nodes, 64>>>((const uint4*)hh1, indptr, csr, (uint4*)aggh);
    gin_hgemm<2, true, true><<<gGrid, 128, HSMEM_L>>>(aggh, W1t, b1, hh2, n_nodes, D);

    // Layer 2
    gather_agg_h<<<n_nodes, 64>>>((const uint4*)hh2, indptr, csr, (uint4*)aggh);
    gin_hgemm<2, true, true><<<gGrid, 128, HSMEM_L>>>(aggh, W2t, b2, hh1, n_nodes, D);

    // Classifier
    gin_hgemm<1, false, false><<<cGrid, 64, HSMEM_C>>>(hh1, Wct, bc, (float*)d_out,
                                                       n_nodes, n_cls);
}